// round 14
// baseline (speedup 1.0000x reference)
#include <cuda_runtime.h>
#include <cuda_fp16.h>
#include <math.h>

// S2_GaussianBlur: depthwise circular 10x10 Gaussian blur, 6 x 2048 x 2048 fp32.
// out[r,c] = sum_{t,u} h[t]h[u] * x[(r+t-4)&2047, (c+u-4)&2047]  (separable, symmetric)
//
// Tile 64 x 64, 5 CTAs/SM (reg-trimmed: symmetric taps h[5], 4-row col spans).
//   row pass : 7 LDG.128 -> 16 fp32 mid -> packed fp16 -> 2 STS.128
//   col pass : 13 LDS.64 sliding window; packed fma.rn.f32x2 -> STG.128
// One __syncthreads. All indexing shift/mask (N = 2^11, lanes 4-aligned).

#define N     2048
#define MASK  2047
#define N4    (N / 4)
#define KS    10
#define RAD   4
#define TX    64             // 16 float4 lanes
#define TY    64
#define HY    (TY + KS - 1)  // 73
#define NT    256
#define ROWITEMS (HY * 4)    // 4 groups of 16 cols per mid row = 292

typedef unsigned long long u64;

__device__ __forceinline__ u64 pack2(float lo, float hi) {
    u64 r;
    asm("mov.b64 %0, {%1, %2};" : "=l"(r) : "f"(lo), "f"(hi));
    return r;
}
__device__ __forceinline__ u64 fma2(u64 a, u64 b, u64 c) {
    u64 d;
    asm("fma.rn.f32x2 %0, %1, %2, %3;" : "=l"(d) : "l"(a), "l"(b), "l"(c));
    return d;
}
__device__ __forceinline__ float2 unpack2(u64 v) {
    float lo, hi;
    asm("mov.b64 {%0, %1}, %2;" : "=f"(lo), "=f"(hi) : "l"(v));
    return make_float2(lo, hi);
}

__constant__ float c_mtf[6] = {0.38f, 0.34f, 0.34f, 0.26f, 0.22f, 0.23f};

__global__ __launch_bounds__(NT, 5)
void s2_gaussian_blur_kernel(const float* __restrict__ x, float* __restrict__ out)
{
    // one mid row = 64 halves = 128 B = 16 uint2 (= 8 uint4)
    __shared__ uint2 s_mid[HY * 16];    // 9344 B

    const int tid = threadIdx.x;
    const int ch  = blockIdx.z;

    // --- taps: symmetric (h[t] = h[9-t]) -> only 5 distinct values ---
    float h[5];
    {
        float mtf  = c_mtf[ch];
        float sig2 = 4.0f * (-2.0f * logf(mtf) / (float)(M_PI * M_PI)); // (scale*sigma)^2
        float inv  = -1.0f / (2.0f * sig2);
        float sum  = 0.0f;
        #pragma unroll
        for (int t = 0; t < 5; ++t) {
            float d = (float)t - 4.5f;
            h[t] = expf(d * d * inv);
            sum += h[t];
        }
        float rs = 0.5f / sum;          // each tap appears twice in the sum
        #pragma unroll
        for (int t = 0; t < 5; ++t) h[t] *= rs;
    }
#define HTAP(t) h[(t) < 5 ? (t) : 9 - (t)]

    const float4* __restrict__ x4 =
        reinterpret_cast<const float4*>(x) + (size_t)ch * N * N4;
    const int row0 = blockIdx.y * TY - RAD;
    const int col0 = blockIdx.x * TX;

    // --- row pass: 73 rows x 4 groups of 16 cols; 7 LDG.128 -> 16 mid -> fp16 ---
    uint4* __restrict__ s_mid4 = reinterpret_cast<uint4*>(s_mid);
    #pragma unroll
    for (int it = 0; it < (ROWITEMS + NT - 1) / NT; ++it) {
        int idx = tid + it * NT;
        if (idx < ROWITEMS) {
            int ly = idx >> 2;           // mid row 0..72
            int g  = idx & 3;            // 16-col group
            const size_t rbase = (size_t)((row0 + ly) & MASK) * N4;
            float a[28];
            #pragma unroll
            for (int k = 0; k < 7; ++k) {
                int c = (col0 + g * 16 - RAD + 4 * k) & MASK;  // 4-aligned, wrap-safe
                float4 v = x4[rbase + (c >> 2)];
                a[4 * k + 0] = v.x; a[4 * k + 1] = v.y;
                a[4 * k + 2] = v.z; a[4 * k + 3] = v.w;
            }
            float m[16];
            #pragma unroll
            for (int o = 0; o < 16; ++o) m[o] = 0.0f;
            #pragma unroll
            for (int t = 0; t < KS; ++t) {
                float ht = HTAP(t);
                #pragma unroll
                for (int o = 0; o < 16; ++o)
                    m[o] = fmaf(ht, a[o + t], m[o]);
            }
            union { uint4 u[2]; __half2 hh[8]; } P;
            #pragma unroll
            for (int j = 0; j < 8; ++j)
                P.hh[j] = __floats2half2_rn(m[2 * j], m[2 * j + 1]);
            s_mid4[ly * 8 + g * 2 + 0] = P.u[0];
            s_mid4[ly * 8 + g * 2 + 1] = P.u[1];
        }
    }
    __syncthreads();

    // --- col pass: sliding window over fp16 mid, packed f32x2 accumulation ---
    u64 hp[5];                           // broadcast-packed distinct taps
    #pragma unroll
    for (int t = 0; t < 5; ++t) hp[t] = pack2(h[t], h[t]);
#define HPK(t) hp[(t) < 5 ? (t) : 9 - (t)]

    const int g  = tid & 15;             // float4 column group
    const int rb = (tid >> 4) * 4;       // output row block 0..60
    u64 accA[4], accB[4];                // accA = cols (0,1), accB = cols (2,3)
    #pragma unroll
    for (int j = 0; j < 4; ++j) { accA[j] = 0ull; accB[j] = 0ull; }

    #pragma unroll
    for (int k = 0; k < KS + 3; ++k) {   // 13 window rows
        uint2 w = s_mid[(rb + k) * 16 + g];          // 4 halves = cols 4g..4g+3
        float2 f0 = __half22float2(*reinterpret_cast<__half2*>(&w.x));
        float2 f1 = __half22float2(*reinterpret_cast<__half2*>(&w.y));
        u64 b0 = pack2(f0.x, f0.y);
        u64 b1 = pack2(f1.x, f1.y);
        #pragma unroll
        for (int j = 0; j < 4; ++j) {
            int t = k - j;
            if (t >= 0 && t < KS) {
                accA[j] = fma2(HPK(t), b0, accA[j]);
                accB[j] = fma2(HPK(t), b1, accB[j]);
            }
        }
    }

    float4* __restrict__ o4 =
        reinterpret_cast<float4*>(out) + (size_t)ch * N * N4;
    const int R0 = blockIdx.y * TY;
    const int oc = (col0 >> 2) + g;
    #pragma unroll
    for (int j = 0; j < 4; ++j) {
        float2 lo = unpack2(accA[j]);
        float2 hi = unpack2(accB[j]);
        o4[(size_t)(R0 + rb + j) * N4 + oc] = make_float4(lo.x, lo.y, hi.x, hi.y);
    }
}

extern "C" void kernel_launch(void* const* d_in, const int* in_sizes, int n_in,
                              void* d_out, int out_size)
{
    const float* x = (const float*)d_in[0];   // (1, 6, 2048, 2048) fp32
    float* out = (float*)d_out;

    dim3 grid(N / TX, N / TY, 6);             // 32 x 32 x 6
    s2_gaussian_blur_kernel<<<grid, NT>>>(x, out);
}